// round 4
// baseline (speedup 1.0000x reference)
#include <cuda_runtime.h>

#define NGRAPH 256
#define M      512
#define KNN    6
#define C      32
#define NWARP  16          // 512 threads
#define FINF   3.402823466e38f

// U ping-pong scratch in global (lives in L2: 32MB of 126MB). Allocation-free.
__device__ float g_U0[NGRAPH * M * C];
__device__ float g_U1[NGRAPH * M * C];

struct SmemLayout {
    float4 pos4[M];          //  8 KB  x,y,z,|p|^2
    float  xs[M];            //  2 KB
    int    idx[M * 8];       // 16 KB  (6 used, padded to 8)
    float  hb[NWARP][2][C];  //  4 KB  per-warp h staging (2 nodes)
    float  red[NWARP * C];   //  2 KB
};                           // 32 KB total -> 2 CTAs/SM

__device__ __forceinline__ void kins(float (&bd)[KNN], int (&bi)[KNN],
                                     float xd, int xi)
{
#pragma unroll
    for (int k = 0; k < KNN; k++) {
        bool  p  = xd < bd[k];          // strict: stable (ties keep earlier j)
        float td = bd[k];
        int   ti = bi[k];
        bd[k] = p ? xd : bd[k];
        bi[k] = p ? xi : bi[k];
        xd    = p ? td : xd;
        xi    = p ? ti : xi;
    }
}

__global__ void __launch_bounds__(512, 2) gcn_fused_kernel(
    const float* __restrict__ x,   const float* __restrict__ pos,
    const float* __restrict__ W1a, const float* __restrict__ b1a,
    const float* __restrict__ W2a, const float* __restrict__ b2a,
    const float* __restrict__ W1b, const float* __restrict__ b1b,
    const float* __restrict__ W2b, const float* __restrict__ b2b,
    const float* __restrict__ W1c, const float* __restrict__ b1c,
    const float* __restrict__ W2c, const float* __restrict__ b2c,
    const float* __restrict__ Wr,  const float* __restrict__ brr,
    float* __restrict__ out)
{
    extern __shared__ char smem_raw[];
    SmemLayout& sm = *reinterpret_cast<SmemLayout*>(smem_raw);

    const int b    = blockIdx.x;
    const int tid  = threadIdx.x;
    const int lane = tid & 31;
    const int wid  = tid >> 5;

    float* __restrict__ UA = g_U0 + (size_t)b * M * C;   // A-value scratch
    float* __restrict__ UU = g_U1 + (size_t)b * M * C;   // layer-output u

    // ---- stage pos (+ squared norm) and x ----
    {
        const int n = tid;
        const float* p = pos + ((size_t)b * M + n) * 3;
        float px = p[0], py = p[1], pz = p[2];
        float s = px * px + py * py + pz * pz;
        sm.pos4[n] = make_float4(px, py, pz, s);
        sm.xs[n]   = x[(size_t)b * M + n];
    }
    __syncthreads();

    // ---- brute-force KNN: thread-per-row, predicated top-6 insert ----
    {
        const int n = tid;
        float4 pn = sm.pos4[n];
        float bd[KNN];
        int   bi[KNN];
#pragma unroll
        for (int k = 0; k < KNN; k++) { bd[k] = FINF; bi[k] = 0; }
#pragma unroll 2
        for (int j = 0; j < M; j += 2) {
            float4 pa = sm.pos4[j];
            float4 pb = sm.pos4[j + 1];
            float dota = fmaf(pn.x, pa.x, fmaf(pn.y, pa.y, pn.z * pa.z));
            float dotb = fmaf(pn.x, pb.x, fmaf(pn.y, pb.y, pn.z * pb.z));
            float d2a  = fmaf(-2.0f, dota, pn.w + pa.w);
            float d2b  = fmaf(-2.0f, dotb, pn.w + pb.w);
            if (d2a < bd[KNN - 1]) kins(bd, bi, d2a, j);
            if (d2b < bd[KNN - 1]) kins(bd, bi, d2b, j + 1);
        }
#pragma unroll
        for (int k = 0; k < KNN; k++) sm.idx[n * 8 + k] = bi[k];
    }
    __syncthreads();

    const int base = wid * 32;
    float* hb0 = &sm.hb[wid][0][0];
    float* hb1 = &sm.hb[wid][1][0];

    // ===================== Layer A =====================
    // ph1: a = relu(W1a·[x,pos] + b1a) -> UA   (Cin=4, no staging needed)
    {
        float w10 = W1a[lane * 4 + 0], w11 = W1a[lane * 4 + 1];
        float w12 = W1a[lane * 4 + 2], w13 = W1a[lane * 4 + 3];
        float bb1 = b1a[lane];
#pragma unroll 1
        for (int t = 0; t < 16; t++) {
            int n0 = base + 2 * t, n1 = n0 + 1;
            float4 p0 = sm.pos4[n0]; float x0 = sm.xs[n0];
            float4 p1 = sm.pos4[n1]; float x1 = sm.xs[n1];
            float a0 = fmaf(w10, x0, fmaf(w11, p0.x, fmaf(w12, p0.y, fmaf(w13, p0.z, bb1))));
            float a1 = fmaf(w10, x1, fmaf(w11, p1.x, fmaf(w12, p1.y, fmaf(w13, p1.z, bb1))));
            UA[n0 * C + lane] = fmaxf(a0, 0.0f);
            UA[n1 * C + lane] = fmaxf(a1, 0.0f);
        }
    }
    __syncthreads();
    // ph2: u = W2a·A + b2a -> UU
    {
        float w2r[C];
#pragma unroll
        for (int c = 0; c < C; c++) w2r[c] = W2a[lane * C + c];
        float bb2 = b2a[lane];
#pragma unroll 1
        for (int t = 0; t < 16; t++) {
            int n0 = base + 2 * t, n1 = n0 + 1;
            const float4* r0 = (const float4*)(UA + n0 * C);
            const float4* r1 = (const float4*)(UA + n1 * C);
            float u00 = bb2, u01 = 0.f, u02 = 0.f, u03 = 0.f;
            float u10 = bb2, u11 = 0.f, u12 = 0.f, u13 = 0.f;
#pragma unroll
            for (int q = 0; q < 8; q++) {
                float4 v0 = r0[q], v1 = r1[q];
                u00 = fmaf(w2r[4*q+0], v0.x, u00); u01 = fmaf(w2r[4*q+1], v0.y, u01);
                u02 = fmaf(w2r[4*q+2], v0.z, u02); u03 = fmaf(w2r[4*q+3], v0.w, u03);
                u10 = fmaf(w2r[4*q+0], v1.x, u10); u11 = fmaf(w2r[4*q+1], v1.y, u11);
                u12 = fmaf(w2r[4*q+2], v1.z, u12); u13 = fmaf(w2r[4*q+3], v1.w, u13);
            }
            UU[n0 * C + lane] = (u00 + u01) + (u02 + u03);
            UU[n1 * C + lane] = (u10 + u11) + (u12 + u13);
        }
    }
    __syncthreads();

    // ===================== Layers B, C =====================
    auto layer32 = [&](const float* W1, const float* B1,
                       const float* W2, const float* B2) {
        // ph1: h = relu(max_j UU[j]);  a = relu(W1·h + b1) -> UA
        {
            float w1r[C];
#pragma unroll
            for (int c = 0; c < C; c++) w1r[c] = W1[lane * C + c];
            float bb1 = B1[lane];
#pragma unroll 1
            for (int t = 0; t < 16; t++) {
                int n0 = base + 2 * t, n1 = n0 + 1;
                const int4 ia0 = *(const int4*)&sm.idx[n0 * 8];
                const int2 ib0 = *(const int2*)&sm.idx[n0 * 8 + 4];
                const int4 ia1 = *(const int4*)&sm.idx[n1 * 8];
                const int2 ib1 = *(const int2*)&sm.idx[n1 * 8 + 4];
                float m0 =            UU[ia0.x * C + lane];
                m0 = fmaxf(m0, UU[ia0.y * C + lane]);
                m0 = fmaxf(m0, UU[ia0.z * C + lane]);
                m0 = fmaxf(m0, UU[ia0.w * C + lane]);
                m0 = fmaxf(m0, UU[ib0.x * C + lane]);
                m0 = fmaxf(m0, UU[ib0.y * C + lane]);
                float m1 =            UU[ia1.x * C + lane];
                m1 = fmaxf(m1, UU[ia1.y * C + lane]);
                m1 = fmaxf(m1, UU[ia1.z * C + lane]);
                m1 = fmaxf(m1, UU[ia1.w * C + lane]);
                m1 = fmaxf(m1, UU[ib1.x * C + lane]);
                m1 = fmaxf(m1, UU[ib1.y * C + lane]);
                hb0[lane] = fmaxf(m0, 0.0f);
                hb1[lane] = fmaxf(m1, 0.0f);
                __syncwarp();
                const float4* h40 = (const float4*)hb0;
                const float4* h41 = (const float4*)hb1;
                float a00 = bb1, a01 = 0.f, a02 = 0.f, a03 = 0.f;
                float a10 = bb1, a11 = 0.f, a12 = 0.f, a13 = 0.f;
#pragma unroll
                for (int q = 0; q < 8; q++) {
                    float4 v0 = h40[q], v1 = h41[q];
                    a00 = fmaf(w1r[4*q+0], v0.x, a00); a01 = fmaf(w1r[4*q+1], v0.y, a01);
                    a02 = fmaf(w1r[4*q+2], v0.z, a02); a03 = fmaf(w1r[4*q+3], v0.w, a03);
                    a10 = fmaf(w1r[4*q+0], v1.x, a10); a11 = fmaf(w1r[4*q+1], v1.y, a11);
                    a12 = fmaf(w1r[4*q+2], v1.z, a12); a13 = fmaf(w1r[4*q+3], v1.w, a13);
                }
                UA[n0 * C + lane] = fmaxf((a00 + a01) + (a02 + a03), 0.0f);
                UA[n1 * C + lane] = fmaxf((a10 + a11) + (a12 + a13), 0.0f);
                __syncwarp();
            }
        }
        __syncthreads();
        // ph2: u = W2·A + b2 -> UU   (overwrites gather src only after barrier)
        {
            float w2r[C];
#pragma unroll
            for (int c = 0; c < C; c++) w2r[c] = W2[lane * C + c];
            float bb2 = B2[lane];
#pragma unroll 1
            for (int t = 0; t < 16; t++) {
                int n0 = base + 2 * t, n1 = n0 + 1;
                const float4* r0 = (const float4*)(UA + n0 * C);
                const float4* r1 = (const float4*)(UA + n1 * C);
                float u00 = bb2, u01 = 0.f, u02 = 0.f, u03 = 0.f;
                float u10 = bb2, u11 = 0.f, u12 = 0.f, u13 = 0.f;
#pragma unroll
                for (int q = 0; q < 8; q++) {
                    float4 v0 = r0[q], v1 = r1[q];
                    u00 = fmaf(w2r[4*q+0], v0.x, u00); u01 = fmaf(w2r[4*q+1], v0.y, u01);
                    u02 = fmaf(w2r[4*q+2], v0.z, u02); u03 = fmaf(w2r[4*q+3], v0.w, u03);
                    u10 = fmaf(w2r[4*q+0], v1.x, u10); u11 = fmaf(w2r[4*q+1], v1.y, u11);
                    u12 = fmaf(w2r[4*q+2], v1.z, u12); u13 = fmaf(w2r[4*q+3], v1.w, u13);
                }
                UU[n0 * C + lane] = (u00 + u01) + (u02 + u03);
                UU[n1 * C + lane] = (u10 + u11) + (u12 + u13);
            }
        }
        __syncthreads();
    };
    layer32(W1b, b1b, W2b, b2b);
    layer32(W1c, b1c, W2c, b2c);

    // ============ final gather + relu + global max pool ============
    {
        float g = -FINF;
#pragma unroll 1
        for (int t = 0; t < 32; t++) {
            int n = base + t;
            const int4 ia = *(const int4*)&sm.idx[n * 8];
            const int2 ib = *(const int2*)&sm.idx[n * 8 + 4];
            float m =            UU[ia.x * C + lane];
            m = fmaxf(m, UU[ia.y * C + lane]);
            m = fmaxf(m, UU[ia.z * C + lane]);
            m = fmaxf(m, UU[ia.w * C + lane]);
            m = fmaxf(m, UU[ib.x * C + lane]);
            m = fmaxf(m, UU[ib.y * C + lane]);
            g = fmaxf(g, fmaxf(m, 0.0f));     // relu then pool
        }
        sm.red[wid * C + lane] = g;
    }
    __syncthreads();

    if (wid == 0) {
        float gg = sm.red[lane];
#pragma unroll
        for (int w = 1; w < NWARP; w++)
            gg = fmaxf(gg, sm.red[w * C + lane]);
#pragma unroll
        for (int od = 0; od < 6; od++) {
            float p = Wr[od * C + lane] * gg;
#pragma unroll
            for (int off = 16; off > 0; off >>= 1)
                p += __shfl_xor_sync(0xffffffffu, p, off);
            if (lane == 0) out[b * 6 + od] = p + brr[od];
        }
    }
}

extern "C" void kernel_launch(void* const* d_in, const int* in_sizes, int n_in,
                              void* d_out, int out_size)
{
    const float* x   = (const float*)d_in[0];
    const float* pos = (const float*)d_in[1];
    // d_in[2] = batch (int64), implicit in layout
    const float* W1a = (const float*)d_in[3];
    const float* b1a = (const float*)d_in[4];
    const float* W2a = (const float*)d_in[5];
    const float* b2a = (const float*)d_in[6];
    const float* W1b = (const float*)d_in[7];
    const float* b1b = (const float*)d_in[8];
    const float* W2b = (const float*)d_in[9];
    const float* b2b = (const float*)d_in[10];
    const float* W1c = (const float*)d_in[11];
    const float* b1c = (const float*)d_in[12];
    const float* W2c = (const float*)d_in[13];
    const float* b2c = (const float*)d_in[14];
    const float* Wr  = (const float*)d_in[15];
    const float* brr = (const float*)d_in[16];
    float* out = (float*)d_out;

    const size_t smem = sizeof(SmemLayout);
    cudaFuncSetAttribute(gcn_fused_kernel,
                         cudaFuncAttributeMaxDynamicSharedMemorySize, (int)smem);

    gcn_fused_kernel<<<NGRAPH, 512, smem>>>(
        x, pos,
        W1a, b1a, W2a, b2a,
        W1b, b1b, W2b, b2b,
        W1c, b1c, W2c, b2c,
        Wr, brr, out);
}

// round 5
// speedup vs baseline: 1.2667x; 1.2667x over previous
#include <cuda_runtime.h>

#define NGRAPH 256
#define M      512
#define KNN    6
#define C      32
#define NWARP  16          // 512 threads
#define FINF   3.402823466e38f

typedef unsigned long long ull;

// inter-phase 'a' scratch (streams through L1/L2; 16MB of 126MB L2)
__device__ float g_A[NGRAPH * M * C];

struct __align__(16) SmemLayout {
    float U[M * C];          // 64KB; head aliased as pos4(8KB)+xs(2KB) pre-layerA-ph2
    int   idxb[M * 8];       // 16KB byte-scaled neighbor offsets (idx*128), 6 used
    float hb[NWARP][2][C];   //  4KB per-warp h staging
    float red[NWARP * C];    //  2KB
};                           // ~86KB -> 2 CTAs/SM

static __device__ __forceinline__ ull pk2(float lo, float hi) {
    ull d; asm("mov.b64 %0, {%1, %2};" : "=l"(d) : "f"(lo), "f"(hi)); return d;
}
static __device__ __forceinline__ float2 upk2(ull v) {
    float2 r; asm("mov.b64 {%0, %1}, %2;" : "=f"(r.x), "=f"(r.y) : "l"(v)); return r;
}
static __device__ __forceinline__ ull ffma2(ull a, ull b, ull c) {
    ull d; asm("fma.rn.f32x2 %0, %1, %2, %3;" : "=l"(d) : "l"(a), "l"(b), "l"(c)); return d;
}

__device__ __forceinline__ void kins(float (&bd)[KNN], int (&bi)[KNN],
                                     float xd, int xi)
{
#pragma unroll
    for (int k = 0; k < KNN; k++) {
        bool  p  = xd < bd[k];          // strict: stable (ties keep earlier j)
        float td = bd[k];
        int   ti = bi[k];
        bd[k] = p ? xd : bd[k];
        bi[k] = p ? xi : bi[k];
        xd    = p ? td : xd;
        xi    = p ? ti : xi;
    }
}

__global__ void __launch_bounds__(512, 2) gcn_fused_kernel(
    const float* __restrict__ x,   const float* __restrict__ pos,
    const float* __restrict__ W1a, const float* __restrict__ b1a,
    const float* __restrict__ W2a, const float* __restrict__ b2a,
    const float* __restrict__ W1b, const float* __restrict__ b1b,
    const float* __restrict__ W2b, const float* __restrict__ b2b,
    const float* __restrict__ W1c, const float* __restrict__ b1c,
    const float* __restrict__ W2c, const float* __restrict__ b2c,
    const float* __restrict__ Wr,  const float* __restrict__ brr,
    float* __restrict__ out)
{
    extern __shared__ char smem_raw[];
    SmemLayout& sm = *reinterpret_cast<SmemLayout*>(smem_raw);

    const int b    = blockIdx.x;
    const int tid  = threadIdx.x;
    const int lane = tid & 31;
    const int wid  = tid >> 5;
    const int base = wid * 32;

    float* __restrict__ Ag = g_A + (size_t)b * M * C;

    // pos/xs alias over U's head (dead once layer-A ph2 writes U)
    float4* pos4 = (float4*)sm.U;
    float*  xs   = sm.U + 4 * M;

    // ---- stage pos (+ squared norm) and x ----
    {
        const int n = tid;
        const float* p = pos + ((size_t)b * M + n) * 3;
        float px = p[0], py = p[1], pz = p[2];
        float s = px * px + py * py + pz * pz;
        pos4[n] = make_float4(px, py, pz, s);
        xs[n]   = x[(size_t)b * M + n];
    }
    __syncthreads();

    // ---- brute-force KNN: thread-per-row, predicated top-6 insert ----
    {
        const int n = tid;
        float4 pn = pos4[n];
        float bd[KNN];
        int   bi[KNN];
#pragma unroll
        for (int k = 0; k < KNN; k++) { bd[k] = FINF; bi[k] = 0; }
#pragma unroll 2
        for (int j = 0; j < M; j += 2) {
            float4 pa = pos4[j];
            float4 pb = pos4[j + 1];
            float dota = fmaf(pn.x, pa.x, fmaf(pn.y, pa.y, pn.z * pa.z));
            float dotb = fmaf(pn.x, pb.x, fmaf(pn.y, pb.y, pn.z * pb.z));
            float d2a  = fmaf(-2.0f, dota, pn.w + pa.w);
            float d2b  = fmaf(-2.0f, dotb, pn.w + pb.w);
            if (d2a < bd[KNN - 1]) kins(bd, bi, d2a, j);
            if (d2b < bd[KNN - 1]) kins(bd, bi, d2b, j + 1);
        }
#pragma unroll
        for (int k = 0; k < KNN; k++) sm.idxb[n * 8 + k] = bi[k] << 7; // byte offset
    }
    __syncthreads();

    float* hb0 = &sm.hb[wid][0][0];
    float* hb1 = &sm.hb[wid][1][0];

    // ---------- ph2 (shared by all layers): u = W2·A(own rows) + b2 -> U (in place)
    auto ph2 = [&](const float* __restrict__ W2, const float* __restrict__ B2) {
        ull wp[16];
#pragma unroll
        for (int t = 0; t < 16; t++) {
            float2 wv = ((const float2*)W2)[lane * 16 + t];
            wp[t] = pk2(wv.x, wv.y);
        }
        float bb = B2[lane];
#pragma unroll 1
        for (int t = 0; t < 16; t++) {
            int n0 = base + 2 * t, n1 = n0 + 1;
            const ulonglong2* r0 = (const ulonglong2*)(Ag + n0 * C);
            const ulonglong2* r1 = (const ulonglong2*)(Ag + n1 * C);
            ull a00 = 0, a01 = 0, a10 = 0, a11 = 0;
#pragma unroll
            for (int q = 0; q < 8; q++) {
                ulonglong2 v0 = r0[q], v1 = r1[q];
                a00 = ffma2(wp[2*q], v0.x, a00); a01 = ffma2(wp[2*q+1], v0.y, a01);
                a10 = ffma2(wp[2*q], v1.x, a10); a11 = ffma2(wp[2*q+1], v1.y, a11);
            }
            float2 e0 = upk2(a00), e1 = upk2(a01);
            float2 e2 = upk2(a10), e3 = upk2(a11);
            sm.U[n0 * C + lane] = bb + ((e0.x + e0.y) + (e1.x + e1.y));
            sm.U[n1 * C + lane] = bb + ((e2.x + e2.y) + (e3.x + e3.y));
        }
    };

    // ===================== layer A ph1: a = relu(W1a·[x,pos]+b1a) -> Ag ==========
    {
        float w10 = W1a[lane * 4 + 0], w11 = W1a[lane * 4 + 1];
        float w12 = W1a[lane * 4 + 2], w13 = W1a[lane * 4 + 3];
        float bb1 = b1a[lane];
#pragma unroll 1
        for (int t = 0; t < 16; t++) {
            int n0 = base + 2 * t, n1 = n0 + 1;
            float4 p0 = pos4[n0]; float x0 = xs[n0];
            float4 p1 = pos4[n1]; float x1 = xs[n1];
            float a0 = fmaf(w10, x0, fmaf(w11, p0.x, fmaf(w12, p0.y, fmaf(w13, p0.z, bb1))));
            float a1 = fmaf(w10, x1, fmaf(w11, p1.x, fmaf(w12, p1.y, fmaf(w13, p1.z, bb1))));
            Ag[n0 * C + lane] = fmaxf(a0, 0.0f);
            Ag[n1 * C + lane] = fmaxf(a1, 0.0f);
        }
    }
    __syncthreads();              // pos4/xs alias dead; U writable
    ph2(W2a, b2a);
    __syncthreads();

    // ===================== layers B, C =====================
    auto ph1_32 = [&](const float* __restrict__ W1, const float* __restrict__ B1) {
        ull wp[16];
#pragma unroll
        for (int t = 0; t < 16; t++) {
            float2 wv = ((const float2*)W1)[lane * 16 + t];
            wp[t] = pk2(wv.x, wv.y);
        }
        float bb = B1[lane];
        const char* Ub = (const char*)sm.U + lane * 4;
#pragma unroll 1
        for (int t = 0; t < 16; t++) {
            int n0 = base + 2 * t, n1 = n0 + 1;
            const int4 ia0 = *(const int4*)&sm.idxb[n0 * 8];
            const int2 ib0 = *(const int2*)&sm.idxb[n0 * 8 + 4];
            const int4 ia1 = *(const int4*)&sm.idxb[n1 * 8];
            const int2 ib1 = *(const int2*)&sm.idxb[n1 * 8 + 4];
            float m0 =            *(const float*)(Ub + ia0.x);
            m0 = fmaxf(m0, *(const float*)(Ub + ia0.y));
            m0 = fmaxf(m0, *(const float*)(Ub + ia0.z));
            m0 = fmaxf(m0, *(const float*)(Ub + ia0.w));
            m0 = fmaxf(m0, *(const float*)(Ub + ib0.x));
            m0 = fmaxf(m0, *(const float*)(Ub + ib0.y));
            float m1 =            *(const float*)(Ub + ia1.x);
            m1 = fmaxf(m1, *(const float*)(Ub + ia1.y));
            m1 = fmaxf(m1, *(const float*)(Ub + ia1.z));
            m1 = fmaxf(m1, *(const float*)(Ub + ia1.w));
            m1 = fmaxf(m1, *(const float*)(Ub + ib1.x));
            m1 = fmaxf(m1, *(const float*)(Ub + ib1.y));
            hb0[lane] = fmaxf(m0, 0.0f);
            hb1[lane] = fmaxf(m1, 0.0f);
            __syncwarp();
            const ulonglong2* h0 = (const ulonglong2*)hb0;
            const ulonglong2* h1 = (const ulonglong2*)hb1;
            ull a00 = 0, a01 = 0, a10 = 0, a11 = 0;
#pragma unroll
            for (int q = 0; q < 8; q++) {
                ulonglong2 v0 = h0[q], v1 = h1[q];
                a00 = ffma2(wp[2*q], v0.x, a00); a01 = ffma2(wp[2*q+1], v0.y, a01);
                a10 = ffma2(wp[2*q], v1.x, a10); a11 = ffma2(wp[2*q+1], v1.y, a11);
            }
            float2 e0 = upk2(a00), e1 = upk2(a01);
            float2 e2 = upk2(a10), e3 = upk2(a11);
            Ag[n0 * C + lane] = fmaxf(bb + ((e0.x + e0.y) + (e1.x + e1.y)), 0.0f);
            Ag[n1 * C + lane] = fmaxf(bb + ((e2.x + e2.y) + (e3.x + e3.y)), 0.0f);
            __syncwarp();
        }
    };

    ph1_32(W1b, b1b);
    __syncthreads();
    ph2(W2b, b2b);
    __syncthreads();

    ph1_32(W1c, b1c);
    __syncthreads();
    ph2(W2c, b2c);
    __syncthreads();

    // ============ final gather + relu + global max pool ============
    {
        const char* Ub = (const char*)sm.U + lane * 4;
        float g = -FINF;
#pragma unroll 1
        for (int t = 0; t < 32; t++) {
            int n = base + t;
            const int4 ia = *(const int4*)&sm.idxb[n * 8];
            const int2 ib = *(const int2*)&sm.idxb[n * 8 + 4];
            float m =            *(const float*)(Ub + ia.x);
            m = fmaxf(m, *(const float*)(Ub + ia.y));
            m = fmaxf(m, *(const float*)(Ub + ia.z));
            m = fmaxf(m, *(const float*)(Ub + ia.w));
            m = fmaxf(m, *(const float*)(Ub + ib.x));
            m = fmaxf(m, *(const float*)(Ub + ib.y));
            g = fmaxf(g, fmaxf(m, 0.0f));     // relu then pool
        }
        sm.red[wid * C + lane] = g;
    }
    __syncthreads();

    if (wid == 0) {
        float gg = sm.red[lane];
#pragma unroll
        for (int w = 1; w < NWARP; w++)
            gg = fmaxf(gg, sm.red[w * C + lane]);
#pragma unroll
        for (int od = 0; od < 6; od++) {
            float p = Wr[od * C + lane] * gg;
#pragma unroll
            for (int off = 16; off > 0; off >>= 1)
                p += __shfl_xor_sync(0xffffffffu, p, off);
            if (lane == 0) out[b * 6 + od] = p + brr[od];
        }
    }
}

extern "C" void kernel_launch(void* const* d_in, const int* in_sizes, int n_in,
                              void* d_out, int out_size)
{
    const float* x   = (const float*)d_in[0];
    const float* pos = (const float*)d_in[1];
    // d_in[2] = batch (int64), implicit in layout
    const float* W1a = (const float*)d_in[3];
    const float* b1a = (const float*)d_in[4];
    const float* W2a = (const float*)d_in[5];
    const float* b2a = (const float*)d_in[6];
    const float* W1b = (const float*)d_in[7];
    const float* b1b = (const float*)d_in[8];
    const float* W2b = (const float*)d_in[9];
    const float* b2b = (const float*)d_in[10];
    const float* W1c = (const float*)d_in[11];
    const float* b1c = (const float*)d_in[12];
    const float* W2c = (const float*)d_in[13];
    const float* b2c = (const float*)d_in[14];
    const float* Wr  = (const float*)d_in[15];
    const float* brr = (const float*)d_in[16];
    float* out = (float*)d_out;

    const size_t smem = sizeof(SmemLayout);
    cudaFuncSetAttribute(gcn_fused_kernel,
                         cudaFuncAttributeMaxDynamicSharedMemorySize, (int)smem);

    gcn_fused_kernel<<<NGRAPH, 512, smem>>>(
        x, pos,
        W1a, b1a, W2a, b2a,
        W1b, b1b, W2b, b2b,
        W1c, b1c, W2c, b2c,
        Wr, brr, out);
}